// round 14
// baseline (speedup 1.0000x reference)
#include <cuda_runtime.h>
#include <cuda_fp16.h>
#include <cstdint>

#define B_ 4
#define N_ 8192
#define D_ 16
#define MIN_PTS_ 10

#define TPB 128                 // 4 warps
#define NBLK 64                 // 128-row blocks per batch
#define NPAIRS (NBLK * (NBLK + 1) / 2)   // 2080
#define CT 128                  // tile edge
#define NT 16                   // 8-col n-subtiles
#define SCSTRIDE 12             // words per candidate row (conflict-free)

__device__ int g_cnt[B_ * N_];

__device__ __forceinline__ float rh(float x) {          // round-to-f16 value
    return __half2float(__float2half_rn(x));
}
__device__ __forceinline__ uint32_t h2u(__half2 v) { return *reinterpret_cast<uint32_t*>(&v); }
__device__ __forceinline__ __half2 u2h(uint32_t v) { return *reinterpret_cast<__half2*>(&v); }
__device__ __forceinline__ __half2 shfl_xor_h2(__half2 v, int m) {
    return u2h(__shfl_xor_sync(0xFFFFFFFF, h2u(v), m));
}

// D = A*B + C, f16 accumulators
__device__ __forceinline__ void mma16816_f16(uint32_t& d0, uint32_t& d1,
                                             const uint32_t a[4],
                                             uint32_t b0, uint32_t b1,
                                             uint32_t c0, uint32_t c1) {
    asm volatile(
        "mma.sync.aligned.m16n8k16.row.col.f16.f16.f16.f16 "
        "{%0,%1}, {%2,%3,%4,%5}, {%6,%7}, {%8,%9};"
        : "=r"(d0), "=r"(d1)
        : "r"(a[0]), "r"(a[1]), "r"(a[2]), "r"(a[3]),
          "r"(b0), "r"(b1), "r"(c0), "r"(c1));
}

__global__ __launch_bounds__(TPB)
void dbscan_sym_kernel(const float* __restrict__ pf) {
    __shared__ uint32_t scu[CT * SCSTRIDE];          // candidate (col) tile, f16 pairs
    __shared__ __align__(4) __half2 snt[CT / 2];     // (-t) pairs, +0.125 folded
    __shared__ float sq[CT][17];                     // row tile staging (f16-rounded)
    __shared__ __half2 scol[4][NT * 4];              // per-warp column partials

    const int tid  = threadIdx.x;
    const int warp = tid >> 5;
    const int lane = tid & 31;
    const int g    = lane >> 2;                 // 0..7
    const int tg   = lane & 3;                  // 0..3
    const int b    = blockIdx.y;
    const float* X = pf + (size_t)b * N_ * D_;

    // ---- Triangular decode: blockIdx.x -> (P, R), P <= R ----
    int P = 0, rem = blockIdx.x, rowlen = NBLK;
    while (rem >= rowlen) { rem -= rowlen; P++; rowlen--; }
    const int R = P + rem;
    const bool offdiag = (P != R);
    const int qbase = P * CT;
    const int cbase = R * CT;

    // ---- Stage row tile (P block) ----
    for (int i = tid; i < CT * 4; i += TPB) {
        const int r = i >> 2, c4 = i & 3;
        float4 v = ((const float4*)(X + (size_t)(qbase + r) * D_))[c4];
        sq[r][c4 * 4 + 0] = rh(v.x); sq[r][c4 * 4 + 1] = rh(v.y);
        sq[r][c4 * 4 + 2] = rh(v.z); sq[r][c4 * 4 + 3] = rh(v.w);
    }

    // ---- Stage col tile (R block): thread tid -> row tid ----
    {
        const float4* cr = (const float4*)(X + (size_t)(cbase + tid) * D_);
        float4 v0 = cr[0], v1 = cr[1], v2 = cr[2], v3 = cr[3];
        float c[16] = {rh(v0.x),rh(v0.y),rh(v0.z),rh(v0.w), rh(v1.x),rh(v1.y),rh(v1.z),rh(v1.w),
                       rh(v2.x),rh(v2.y),rh(v2.z),rh(v2.w), rh(v3.x),rh(v3.y),rh(v3.z),rh(v3.w)};
        float s = 0.f;
        #pragma unroll
        for (int k = 0; k < 16; k++) s = fmaf(c[k], c[k], s);
        uint32_t* row = scu + tid * SCSTRIDE;
        #pragma unroll
        for (int e = 0; e < 8; e++)
            row[e] = h2u(__floats2half2_rn(c[2 * e], c[2 * e + 1]));
        ((__half*)snt)[tid] = __float2half_rn(0.125f - 0.5f * s);
    }
    __syncthreads();

    // ---- A fragments (rows r0, r0+8, r0+16, r0+24) + nh broadcasts ----
    const int r0 = warp * 32 + g;
    uint32_t alo[4], ahi[4], nhp[4];
    #pragma unroll
    for (int blk = 0; blk < 2; blk++) {
        const int ra = r0 + blk * 16, rbw = ra + 8;
        uint32_t* a = blk ? ahi : alo;
        a[0] = h2u(__floats2half2_rn(sq[ra][2 * tg],      sq[ra][2 * tg + 1]));
        a[1] = h2u(__floats2half2_rn(sq[rbw][2 * tg],     sq[rbw][2 * tg + 1]));
        a[2] = h2u(__floats2half2_rn(sq[ra][2 * tg + 8],  sq[ra][2 * tg + 9]));
        a[3] = h2u(__floats2half2_rn(sq[rbw][2 * tg + 8], sq[rbw][2 * tg + 9]));
        float s0 = 0.f, s1 = 0.f;
        #pragma unroll
        for (int k = 0; k < D_; k++) {
            s0 = fmaf(sq[ra][k], sq[ra][k], s0);
            s1 = fmaf(sq[rbw][k], sq[rbw][k], s1);
        }
        nhp[blk * 2 + 0] = h2u(__float2half2_rn(-0.5f * s0));
        nhp[blk * 2 + 1] = h2u(__float2half2_rn(-0.5f * s1));
    }

    const __half2 zero2 = __float2half2_rn(0.0f);
    __half2 acc0 = zero2, acc1 = zero2, acc2 = zero2, acc3 = zero2;

    #pragma unroll 4
    for (int nt = 0; nt < NT; nt++) {
        const uint32_t* row = scu + (nt * 8 + g) * SCSTRIDE;
        const uint32_t b0 = row[tg];
        const uint32_t b1 = row[tg + 4];
        const __half2 ntv = snt[nt * 4 + tg];       // cols 2tg, 2tg+1
        const uint32_t c0 = h2u(__hadd2(u2h(nhp[0]), ntv));
        const uint32_t c1 = h2u(__hadd2(u2h(nhp[1]), ntv));
        const uint32_t c2 = h2u(__hadd2(u2h(nhp[2]), ntv));
        const uint32_t c3 = h2u(__hadd2(u2h(nhp[3]), ntv));
        uint32_t d0, d1, d2, d3;
        mma16816_f16(d0, d1, alo, b0, b1, c0, c1);
        mma16816_f16(d2, d3, ahi, b0, b1, c2, c3);
        const __half2 t0 = __hgt2(u2h(d0), zero2);
        const __half2 t1 = __hgt2(u2h(d1), zero2);
        const __half2 t2 = __hgt2(u2h(d2), zero2);
        const __half2 t3 = __hgt2(u2h(d3), zero2);
        acc0 = __hadd2(acc0, t0);
        acc1 = __hadd2(acc1, t1);
        acc2 = __hadd2(acc2, t2);
        acc3 = __hadd2(acc3, t3);
        if (offdiag) {
            // column partial over this lane's 4 rows, then reduce over g-lanes
            __half2 cp = __hadd2(__hadd2(t0, t1), __hadd2(t2, t3));
            cp = __hadd2(cp, shfl_xor_h2(cp, 4));
            cp = __hadd2(cp, shfl_xor_h2(cp, 8));
            cp = __hadd2(cp, shfl_xor_h2(cp, 16));
            if (g == 0) scol[warp][nt * 4 + tg] = cp;   // cols nt*8+2tg, +1
        }
    }

    // ---- Row counts -> atomic ----
    int cnt[4];
    cnt[0] = (int)(__low2float(acc0) + __high2float(acc0));
    cnt[1] = (int)(__low2float(acc1) + __high2float(acc1));
    cnt[2] = (int)(__low2float(acc2) + __high2float(acc2));
    cnt[3] = (int)(__low2float(acc3) + __high2float(acc3));
    #pragma unroll
    for (int r = 0; r < 4; r++) {
        cnt[r] += __shfl_xor_sync(0xFFFFFFFF, cnt[r], 1);
        cnt[r] += __shfl_xor_sync(0xFFFFFFFF, cnt[r], 2);
    }
    if (tg == 0) {
        #pragma unroll
        for (int r = 0; r < 4; r++)
            atomicAdd(&g_cnt[b * N_ + qbase + r0 + r * 8], cnt[r]);
    }

    // ---- Column counts (off-diagonal only): cross-warp sum, 1 atomic/col ----
    if (offdiag) {
        __syncthreads();
        if (tid < NT * 4) {
            const int s = tid;
            __half2 tot = __hadd2(__hadd2(scol[0][s], scol[1][s]),
                                  __hadd2(scol[2][s], scol[3][s]));
            const int nt = s >> 2, tg2 = s & 3;
            const int colg = b * N_ + cbase + nt * 8 + 2 * tg2;
            atomicAdd(&g_cnt[colg],     (int)__low2float(tot));
            atomicAdd(&g_cnt[colg + 1], (int)__high2float(tot));
        }
    }
}

// ---------------- reduce kernel (float output: harness compares as f32) ----------------
__global__ void dbscan_reduce_kernel(float* __restrict__ out) {
    const int idx = blockIdx.x * blockDim.x + threadIdx.x;
    if (idx < B_ * N_) {
        out[idx] = (g_cnt[idx] < MIN_PTS_) ? -1.0f : 0.0f;
    }
}

extern "C" void kernel_launch(void* const* d_in, const int* in_sizes, int n_in,
                              void* d_out, int out_size) {
    const float* pf = (const float*)d_in[0];
    float* out = (float*)d_out;
    (void)in_sizes; (void)n_in; (void)out_size;

    void* gaddr = nullptr;
    cudaGetSymbolAddress(&gaddr, g_cnt);
    cudaMemsetAsync(gaddr, 0, sizeof(int) * B_ * N_);   // memset node: capturable

    dim3 grid(NPAIRS, B_, 1);   // 2080 x 4 = 8320 CTAs
    dbscan_sym_kernel<<<grid, TPB>>>(pf);
    dbscan_reduce_kernel<<<(B_ * N_ + 255) / 256, 256>>>(out);
}

// round 16
// speedup vs baseline: 1.2243x; 1.2243x over previous
#include <cuda_runtime.h>
#include <cuda_fp16.h>
#include <cstdint>

#define B_ 4
#define N_ 8192
#define D_ 16
#define MIN_PTS_ 10

#define TPB 128                 // 4 warps
#define NBLK 64                 // 128-row blocks per batch
#define CT 128                  // tile edge
#define NT 16                   // 8-col n-subtiles
#define SCSTRIDE 12             // words per candidate row (conflict-free)
#define PARTS 4                 // CTAs per strip
#define SPP 8                   // s-offsets per part

__device__ int g_cnt[B_ * N_];

__device__ __forceinline__ float rh(float x) {          // round-to-f16 value
    return __half2float(__float2half_rn(x));
}
__device__ __forceinline__ uint32_t h2u(__half2 v) { return *reinterpret_cast<uint32_t*>(&v); }
__device__ __forceinline__ __half2 u2h(uint32_t v) { return *reinterpret_cast<__half2*>(&v); }
__device__ __forceinline__ __half2 shfl_xor_h2(__half2 v, int m) {
    return u2h(__shfl_xor_sync(0xFFFFFFFF, h2u(v), m));
}

// D = A*B + C, f16 accumulators
__device__ __forceinline__ void mma16816_f16(uint32_t& d0, uint32_t& d1,
                                             const uint32_t a[4],
                                             uint32_t b0, uint32_t b1,
                                             uint32_t c0, uint32_t c1) {
    asm volatile(
        "mma.sync.aligned.m16n8k16.row.col.f16.f16.f16.f16 "
        "{%0,%1}, {%2,%3,%4,%5}, {%6,%7}, {%8,%9};"
        : "=r"(d0), "=r"(d1)
        : "r"(a[0]), "r"(a[1]), "r"(a[2]), "r"(a[3]),
          "r"(b0), "r"(b1), "r"(c0), "r"(c1));
}

// Stage candidate row (thread tid -> local row tid) from global row (cbase+tid).
__device__ __forceinline__ void stage_row(uint32_t* scu, __half2* snt, int tid,
                                          float4 v0, float4 v1, float4 v2, float4 v3) {
    float c[16] = {rh(v0.x),rh(v0.y),rh(v0.z),rh(v0.w), rh(v1.x),rh(v1.y),rh(v1.z),rh(v1.w),
                   rh(v2.x),rh(v2.y),rh(v2.z),rh(v2.w), rh(v3.x),rh(v3.y),rh(v3.z),rh(v3.w)};
    float s = 0.f;
    #pragma unroll
    for (int k = 0; k < 16; k++) s = fmaf(c[k], c[k], s);
    uint32_t* row = scu + tid * SCSTRIDE;
    #pragma unroll
    for (int e = 0; e < 8; e++)
        row[e] = h2u(__floats2half2_rn(c[2 * e], c[2 * e + 1]));
    ((__half*)snt)[tid] = __float2half_rn(0.125f - 0.5f * s);
}

__global__ __launch_bounds__(TPB)
void dbscan_sym_kernel(const float* __restrict__ pf) {
    __shared__ uint32_t scu[2][CT * SCSTRIDE];       // col tiles, double-buffered (12 KB)
    __shared__ __align__(4) __half2 snt[2][CT / 2];  // (-t) pairs +0.125 folded
    __shared__ float sq[CT][17];                     // query tile staging (8.5 KB)
    __shared__ __half2 scol[2][4][NT * 4];           // per-warp column partials (2 KB)

    const int tid  = threadIdx.x;
    const int warp = tid >> 5;
    const int lane = tid & 31;
    const int g    = lane >> 2;                 // 0..7
    const int tg   = lane & 3;                  // 0..3
    const int b    = blockIdx.y;
    const float* X = pf + (size_t)b * N_ * D_;

    const int P = blockIdx.x >> 2;              // strip (query block)
    const int m = blockIdx.x & 3;               // part
    const int ntiles = SPP + ((m == 3 && P < 32) ? 1 : 0);
    const int qbase = P * CT;

    // s(i): offsets m*8..m*8+7, plus s=32 as 9th tile for part 3 of P<32
    #define S_OF(i) (((i) < SPP) ? (m * SPP + (i)) : 32)
    #define R_OF(i) (((P + S_OF(i)) & (NBLK - 1)) * CT)

    // ---- Stage query tile (once) ----
    for (int i = tid; i < CT * 4; i += TPB) {
        const int r = i >> 2, c4 = i & 3;
        float4 v = ((const float4*)(X + (size_t)(qbase + r) * D_))[c4];
        sq[r][c4 * 4 + 0] = rh(v.x); sq[r][c4 * 4 + 1] = rh(v.y);
        sq[r][c4 * 4 + 2] = rh(v.z); sq[r][c4 * 4 + 3] = rh(v.w);
    }

    // ---- Stage first col tile into buffer 0 ----
    {
        const float4* cr = (const float4*)(X + (size_t)(R_OF(0) + tid) * D_);
        stage_row(scu[0], snt[0], tid, cr[0], cr[1], cr[2], cr[3]);
    }
    __syncthreads();

    // ---- A fragments (rows r0, r0+8, r0+16, r0+24) + nh broadcasts (once) ----
    const int r0 = warp * 32 + g;
    uint32_t alo[4], ahi[4], nhp[4];
    #pragma unroll
    for (int blk = 0; blk < 2; blk++) {
        const int ra = r0 + blk * 16, rbw = ra + 8;
        uint32_t* a = blk ? ahi : alo;
        a[0] = h2u(__floats2half2_rn(sq[ra][2 * tg],      sq[ra][2 * tg + 1]));
        a[1] = h2u(__floats2half2_rn(sq[rbw][2 * tg],     sq[rbw][2 * tg + 1]));
        a[2] = h2u(__floats2half2_rn(sq[ra][2 * tg + 8],  sq[ra][2 * tg + 9]));
        a[3] = h2u(__floats2half2_rn(sq[rbw][2 * tg + 8], sq[rbw][2 * tg + 9]));
        float s0 = 0.f, s1 = 0.f;
        #pragma unroll
        for (int k = 0; k < D_; k++) {
            s0 = fmaf(sq[ra][k], sq[ra][k], s0);
            s1 = fmaf(sq[rbw][k], sq[rbw][k], s1);
        }
        nhp[blk * 2 + 0] = h2u(__float2half2_rn(-0.5f * s0));
        nhp[blk * 2 + 1] = h2u(__float2half2_rn(-0.5f * s1));
    }

    const __half2 zero2 = __float2half2_rn(0.0f);
    __half2 acc0 = zero2, acc1 = zero2, acc2 = zero2, acc3 = zero2;
    int p = 0;

    for (int it = 0; it < ntiles; it++) {
        const bool more = (it + 1 < ntiles);
        float4 nv0, nv1, nv2, nv3;                 // prefetch next col tile
        if (more) {
            const float4* cr = (const float4*)(X + (size_t)(R_OF(it + 1) + tid) * D_);
            nv0 = cr[0]; nv1 = cr[1]; nv2 = cr[2]; nv3 = cr[3];
        }

        const uint32_t* bufc = scu[p];
        const __half2*  buft = snt[p];
        #pragma unroll 4
        for (int nt = 0; nt < NT; nt++) {
            const uint32_t* row = bufc + (nt * 8 + g) * SCSTRIDE;
            const uint32_t b0 = row[tg];
            const uint32_t b1 = row[tg + 4];
            const __half2 ntv = buft[nt * 4 + tg];      // cols 2tg, 2tg+1
            const uint32_t c0 = h2u(__hadd2(u2h(nhp[0]), ntv));
            const uint32_t c1 = h2u(__hadd2(u2h(nhp[1]), ntv));
            const uint32_t c2 = h2u(__hadd2(u2h(nhp[2]), ntv));
            const uint32_t c3 = h2u(__hadd2(u2h(nhp[3]), ntv));
            uint32_t d0, d1, d2, d3;
            mma16816_f16(d0, d1, alo, b0, b1, c0, c1);
            mma16816_f16(d2, d3, ahi, b0, b1, c2, c3);
            const __half2 t0 = __hgt2(u2h(d0), zero2);
            const __half2 t1 = __hgt2(u2h(d1), zero2);
            const __half2 t2 = __hgt2(u2h(d2), zero2);
            const __half2 t3 = __hgt2(u2h(d3), zero2);
            acc0 = __hadd2(acc0, t0);
            acc1 = __hadd2(acc1, t1);
            acc2 = __hadd2(acc2, t2);
            acc3 = __hadd2(acc3, t3);
            // column partial over this lane's 4 rows, reduced over the 8 g-lanes
            __half2 cp = __hadd2(__hadd2(t0, t1), __hadd2(t2, t3));
            cp = __hadd2(cp, shfl_xor_h2(cp, 4));
            cp = __hadd2(cp, shfl_xor_h2(cp, 8));
            cp = __hadd2(cp, shfl_xor_h2(cp, 16));
            if (g == 0) scol[p][warp][nt * 4 + tg] = cp;   // cols nt*8+2tg, +1
        }

        if (more) {
            stage_row(scu[p ^ 1], snt[p ^ 1], tid, nv0, nv1, nv2, nv3);
        }
        __syncthreads();   // buf p read by all; buf p^1 staged; scol[p] complete

        // Column atomics for tile just computed (skip diagonal s==0).
        // Runs concurrent with next iteration's compute on buf p^1 (scol double-buffered).
        if (S_OF(it) != 0 && tid < NT * 4) {
            const __half2 tot = __hadd2(__hadd2(scol[p][0][tid], scol[p][1][tid]),
                                        __hadd2(scol[p][2][tid], scol[p][3][tid]));
            const int nt = tid >> 2, tg2 = tid & 3;
            const int colg = b * N_ + R_OF(it) + nt * 8 + 2 * tg2;
            atomicAdd(&g_cnt[colg],     (int)__low2float(tot));
            atomicAdd(&g_cnt[colg + 1], (int)__high2float(tot));
        }
        p ^= 1;
    }

    // ---- Row counts -> atomic (accumulated across all tiles; f16 exact <=144) ----
    int cnt[4];
    cnt[0] = (int)(__low2float(acc0) + __high2float(acc0));
    cnt[1] = (int)(__low2float(acc1) + __high2float(acc1));
    cnt[2] = (int)(__low2float(acc2) + __high2float(acc2));
    cnt[3] = (int)(__low2float(acc3) + __high2float(acc3));
    #pragma unroll
    for (int r = 0; r < 4; r++) {
        cnt[r] += __shfl_xor_sync(0xFFFFFFFF, cnt[r], 1);
        cnt[r] += __shfl_xor_sync(0xFFFFFFFF, cnt[r], 2);
    }
    if (tg == 0) {
        #pragma unroll
        for (int r = 0; r < 4; r++)
            atomicAdd(&g_cnt[b * N_ + qbase + r0 + r * 8], cnt[r]);
    }
    #undef S_OF
    #undef R_OF
}

// ---------------- reduce kernel (float output: harness compares as f32) ----------------
__global__ void dbscan_reduce_kernel(float* __restrict__ out) {
    const int idx = blockIdx.x * blockDim.x + threadIdx.x;
    if (idx < B_ * N_) {
        out[idx] = (g_cnt[idx] < MIN_PTS_) ? -1.0f : 0.0f;
    }
}

extern "C" void kernel_launch(void* const* d_in, const int* in_sizes, int n_in,
                              void* d_out, int out_size) {
    const float* pf = (const float*)d_in[0];
    float* out = (float*)d_out;
    (void)in_sizes; (void)n_in; (void)out_size;

    void* gaddr = nullptr;
    cudaGetSymbolAddress(&gaddr, g_cnt);
    cudaMemsetAsync(gaddr, 0, sizeof(int) * B_ * N_);   // memset node: capturable

    dim3 grid(NBLK * PARTS, B_, 1);   // 256 x 4 = 1024 CTAs, 8-9 tiles each
    dbscan_sym_kernel<<<grid, TPB>>>(pf);
    dbscan_reduce_kernel<<<(B_ * N_ + 255) / 256, 256>>>(out);
}